// round 12
// baseline (speedup 1.0000x reference)
#include <cuda_runtime.h>
#include <cuda_fp16.h>
#include <stdint.h>

// Problem constants
constexpr int B  = 4;
constexpr int N  = 2048;
constexpr int D  = 512;
constexpr int H  = 8;
constexpr int DH = 64;
constexpr float SCALE  = 0.125f;                 // DH^-0.5
constexpr float LOG2E  = 1.4426950408889634f;
constexpr float QSCALE = SCALE * LOG2E;          // folded into Q: p = 2^s

constexpr size_t QKV_ELEMS = (size_t)B * H * N * DH;  // 4,194,304
constexpr size_t X_ELEMS   = (size_t)B * N * D;
constexpr size_t W_ELEMS   = (size_t)3 * H * DH * D;

// fp16 scratch (hi-only everywhere).
__device__ __half g_Xh[X_ELEMS];
__device__ __half g_Wh[W_ELEMS];
// Q: pre-shifted (q_cross), pre-scaled by SCALE*log2e. [bh][row][dh].
__device__ __half g_Qh[QKV_ELEMS];
__device__ __half g_K[QKV_ELEMS];
__device__ __half g_V[QKV_ELEMS];

// ---------------- helpers ----------------
__device__ __forceinline__ uint32_t smem_u32(const void* p) {
    return (uint32_t)__cvta_generic_to_shared(p);
}
__device__ __forceinline__ uint32_t swz(int row, int ch) {
    return (uint32_t)(row * 128 + ((ch ^ (row & 7)) << 4));
}
__device__ __forceinline__ void ldsm4(uint32_t a, uint32_t& r0, uint32_t& r1,
                                      uint32_t& r2, uint32_t& r3) {
    asm volatile("ldmatrix.sync.aligned.m8n8.x4.shared.b16 {%0,%1,%2,%3},[%4];\n"
                 : "=r"(r0), "=r"(r1), "=r"(r2), "=r"(r3) : "r"(a));
}
__device__ __forceinline__ void ldsm4t(uint32_t a, uint32_t& r0, uint32_t& r1,
                                       uint32_t& r2, uint32_t& r3) {
    asm volatile("ldmatrix.sync.aligned.m8n8.x4.trans.shared.b16 {%0,%1,%2,%3},[%4];\n"
                 : "=r"(r0), "=r"(r1), "=r"(r2), "=r"(r3) : "r"(a));
}
// fp32-accum fp16 MMA
__device__ __forceinline__ void mma_h(float* c, uint32_t a0, uint32_t a1,
                                      uint32_t a2, uint32_t a3,
                                      uint32_t b0, uint32_t b1) {
    asm volatile(
        "mma.sync.aligned.m16n8k16.row.col.f32.f16.f16.f32 "
        "{%0,%1,%2,%3},{%4,%5,%6,%7},{%8,%9},{%0,%1,%2,%3};\n"
        : "+f"(c[0]), "+f"(c[1]), "+f"(c[2]), "+f"(c[3])
        : "r"(a0), "r"(a1), "r"(a2), "r"(a3), "r"(b0), "r"(b1));
}
// fp16-accum fp16 MMA (C = 2 regs of packed half2)
__device__ __forceinline__ void mma_h16(uint32_t* c, uint32_t a0, uint32_t a1,
                                        uint32_t a2, uint32_t a3,
                                        uint32_t b0, uint32_t b1) {
    asm volatile(
        "mma.sync.aligned.m16n8k16.row.col.f16.f16.f16.f16 "
        "{%0,%1},{%2,%3,%4,%5},{%6,%7},{%0,%1};\n"
        : "+r"(c[0]), "+r"(c[1])
        : "r"(a0), "r"(a1), "r"(a2), "r"(a3), "r"(b0), "r"(b1));
}
__device__ __forceinline__ uint32_t packh(float x, float y) {
    __half2 v = __floats2half2_rn(x, y);
    return *reinterpret_cast<uint32_t*>(&v);
}
__device__ __forceinline__ void cp16(uint32_t s, const void* g) {
    asm volatile("cp.async.cg.shared.global [%0], [%1], 16;\n" :: "r"(s), "l"(g));
}
__device__ __forceinline__ void cp_commit() {
    asm volatile("cp.async.commit_group;\n");
}
template <int NN> __device__ __forceinline__ void cp_wait() {
    asm volatile("cp.async.wait_group %0;\n" :: "n"(NN));
}

// ---------------------------------------------------------------------------
// Kernel 0: fp32 -> fp16 (hi only), X and W, exactly one float4 per thread
// ---------------------------------------------------------------------------
constexpr int CV_XN4   = (int)(X_ELEMS / 4);           // 1,048,576
constexpr int CV_WN4   = (int)(W_ELEMS / 4);           // 196,608
constexpr int CV_TOTAL = CV_XN4 + CV_WN4;              // 1,245,184
constexpr int CV_GRID  = CV_TOTAL / 256;               // 4864 (exact)

__global__ __launch_bounds__(256) void convert_all(
    const float* __restrict__ x, const float* __restrict__ wt)
{
    const int i = blockIdx.x * 256 + threadIdx.x;
    if (i < CV_XN4) {
        const float4 v = ((const float4*)x)[i];
        ((uint2*)g_Xh)[i] = make_uint2(packh(v.x, v.y), packh(v.z, v.w));
    } else {
        const float4 v = ((const float4*)wt)[i - CV_XN4];
        ((uint2*)g_Wh)[i - CV_XN4] = make_uint2(packh(v.x, v.y), packh(v.z, v.w));
    }
}

// ---------------------------------------------------------------------------
// Kernel 1: QKV projection GEMM, 1-pass fp16, cp.async 3-stage,
// one __syncthreads per k-iter (issue-at-top).
// BM=128, BN=128, BK=64; 8 warps (2m x 4n), warp tile m64 x n32.
// ---------------------------------------------------------------------------
constexpr int G_STAGE = 32768;
constexpr int G_SMEM  = 3 * G_STAGE;   // 96KB

__global__ __launch_bounds__(256, 2) void qkv_gemm()
{
    extern __shared__ __align__(1024) uint8_t sm[];

    const int t = threadIdx.x, lane = t & 31, w = t >> 5;
    const int m0 = blockIdx.y * 128, n0 = blockIdx.x * 128;
    const int wm = w >> 2, wn = w & 3;

    float acc[4][4][4];
#pragma unroll
    for (int f = 0; f < 4; f++)
#pragma unroll
        for (int g = 0; g < 4; g++)
#pragma unroll
            for (int i = 0; i < 4; i++) acc[f][g][i] = 0.f;

    auto issue = [&](int ki) {
        uint8_t* sbase = sm + (ki % 3) * G_STAGE;
        const int k0 = ki * 64;
#pragma unroll
        for (int i = 0; i < 8; i++) {
            const int lin = t + 256 * i;          // 0..2047
            const int arr = lin >> 10, idx = lin & 1023;
            const int row = idx >> 3, ch = idx & 7;
            const __half* src = (arr == 0 ? g_Xh + (size_t)(m0 + row) * D
                                          : g_Wh + (size_t)(n0 + row) * D)
                              + k0 + ch * 8;
            cp16(smem_u32(sbase + arr * 16384 + swz(row, ch)), src);
        }
        cp_commit();
    };

    constexpr int NK = D / 64;   // 8
    issue(0);
    issue(1);

    for (int ki = 0; ki < NK; ki++) {
        if (ki + 1 < NK) cp_wait<1>();
        else             cp_wait<0>();
        __syncthreads();
        if (ki + 2 < NK) issue(ki + 2);

        const uint32_t sA = smem_u32(sm) + (ki % 3) * G_STAGE;
        const uint32_t sB = sA + 16384;

#pragma unroll
        for (int s = 0; s < 4; s++) {
            uint32_t ah[4][4];
#pragma unroll
            for (int f = 0; f < 4; f++) {
                const int row = wm * 64 + f * 16 + (lane & 15);
                const int ch  = 2 * s + (lane >> 4);
                ldsm4(sA + swz(row, ch), ah[f][0], ah[f][1], ah[f][2], ah[f][3]);
            }
            uint32_t bh[4][2];
#pragma unroll
            for (int gp = 0; gp < 4; gp += 2) {
                const int row = wn * 32 + 8 * (gp + (lane >> 4)) + (lane & 7);
                const int ch  = 2 * s + ((lane >> 3) & 1);
                uint32_t r0, r1, r2, r3;
                ldsm4(sB + swz(row, ch), r0, r1, r2, r3);
                bh[gp][0] = r0; bh[gp][1] = r1; bh[gp+1][0] = r2; bh[gp+1][1] = r3;
            }
#pragma unroll
            for (int f = 0; f < 4; f++)
#pragma unroll
                for (int g = 0; g < 4; g++)
                    mma_h(acc[f][g], ah[f][0], ah[f][1], ah[f][2], ah[f][3],
                          bh[g][0], bh[g][1]);
        }
    }

    // Epilogue: fp16 scatter. Q pre-shifted + pre-scaled by SCALE*log2e.
    const int which = n0 >> 9;   // 0=Q, 1=K, 2=V
#pragma unroll
    for (int f = 0; f < 4; f++) {
#pragma unroll
        for (int g = 0; g < 4; g++) {
            const int c  = n0 + wn * 32 + 8 * g + 2 * (lane & 3);
            const int hh = (c >> 6) & 7;
            const int dh = c & 63;
#pragma unroll
            for (int half = 0; half < 2; half++) {
                const int m = m0 + wm * 64 + f * 16 + (lane >> 2) + half * 8;
                float v0 = acc[f][g][half * 2], v1 = acc[f][g][half * 2 + 1];
                const int bb = m >> 11, n = m & 2047;
                const size_t bhN = (size_t)(bb * H + hh) * N;
                if (which == 0) {
                    v0 *= QSCALE; v1 *= QSCALE;
                    const uint32_t hi = packh(v0, v1);
                    if (n < N - 1) *(uint32_t*)(g_Qh + (bhN + n + 1) * DH + dh) = hi;
                    if (n == 0)    *(uint32_t*)(g_Qh + bhN * DH + dh)           = hi;
                } else {
                    const size_t e = (bhN + n) * DH + dh;
                    const uint32_t hi = packh(v0, v1);
                    if (which == 1) *(uint32_t*)(g_K + e) = hi;
                    else            *(uint32_t*)(g_V + e) = hi;
                }
            }
        }
    }
}

// ---------------------------------------------------------------------------
// Kernel 2: flash attention, ping-pong pipeline, 4-stage cp.async ring,
// one __syncthreads per tile. 4 warps, m32 warp tiles, fp16 S-accum,
// ex2 in place, fp32 ones-MMA l. 3 CTAs/SM (waves 1.73 -> 1.15).
// ---------------------------------------------------------------------------
constexpr int AT_STG    = 16384;
constexpr int ATTN_SMEM = 4 * AT_STG;   // 64KB
constexpr int NT = N / 64;   // 32 tiles
constexpr uint32_t ONES_H2 = 0x3C003C00u;   // packed half2 (1.0, 1.0)

__global__ __launch_bounds__(128, 3) void attn(float* __restrict__ out)
{
    extern __shared__ __align__(1024) uint8_t sm[];

    const int t = threadIdx.x, lane = t & 31, w = t >> 5;   // w: 0..3
    const int q0 = blockIdx.x * 128, hh = blockIdx.y, bb = blockIdx.z;
    const size_t base = (size_t)(bb * H + hh) * N * DH;
    const int qrow = q0 + w * 32;                // 32 queries per warp
    const int r4 = lane >> 2, c2 = 2 * (lane & 3);
    const uint32_t smbase = smem_u32(sm);

    auto load_tile = [&](int tt) {
        uint8_t* stg = sm + (tt & 3) * AT_STG;
        const int kt = tt * 64;
#pragma unroll
        for (int i = 0; i < 8; i++) {
            const int g = t + 128 * i;            // 0..1023
            const int arr = g >> 9, idx = g & 511;
            const int row = idx >> 3, ch = idx & 7;
            const __half* src = (arr == 0 ? g_K : g_V)
                              + base + (size_t)(kt + row) * DH + ch * 8;
            cp16(smem_u32(stg + arr * 8192 + swz(row, ch)), src);
        }
        cp_commit();
    };

    // Q A-fragments straight from gmem: two m16 halves
    uint32_t qh[2][4][4];
    {
        const uint32_t* ph = reinterpret_cast<const uint32_t*>(g_Qh + base);
#pragma unroll
        for (int half = 0; half < 2; half++) {
#pragma unroll
            for (int s = 0; s < 4; s++) {
                const int k = s * 16 + c2;
                const int i0 = ((qrow + half * 16 + r4) * DH + k) >> 1;
                const int i1 = ((qrow + half * 16 + r4 + 8) * DH + k) >> 1;
                qh[half][s][0] = ph[i0];     qh[half][s][1] = ph[i1];
                qh[half][s][2] = ph[i0 + 4]; qh[half][s][3] = ph[i1 + 4];
            }
        }
    }

    float o[2][8][4];
#pragma unroll
    for (int half = 0; half < 2; half++)
#pragma unroll
        for (int g = 0; g < 8; g++)
#pragma unroll
            for (int i = 0; i < 4; i++) o[half][g][i] = 0.f;
    float lacc[2][4] = {{0.f, 0.f, 0.f, 0.f}, {0.f, 0.f, 0.f, 0.f}};

    uint32_t ppA[2][8][2], ppB[2][8][2];

    // S phase only (prologue): S(tile) from stage aK into sn, then ex2
    auto s_only = [&](uint32_t aK, uint32_t (&sn)[2][8][2]) {
#pragma unroll
        for (int h = 0; h < 2; h++)
#pragma unroll
            for (int gp = 0; gp < 8; gp++) { sn[h][gp][0] = 0u; sn[h][gp][1] = 0u; }
#pragma unroll
        for (int s = 0; s < 4; s++) {
#pragma unroll
            for (int gp = 0; gp < 8; gp += 2) {
                const int row = 8 * (gp + (lane >> 4)) + (lane & 7);
                const int ch  = 2 * s + ((lane >> 3) & 1);
                uint32_t k0, k1, k2, k3;
                ldsm4(aK + swz(row, ch), k0, k1, k2, k3);
#pragma unroll
                for (int h = 0; h < 2; h++) {
                    mma_h16(sn[h][gp],     qh[h][s][0], qh[h][s][1],
                            qh[h][s][2], qh[h][s][3], k0, k1);
                    mma_h16(sn[h][gp + 1], qh[h][s][0], qh[h][s][1],
                            qh[h][s][2], qh[h][s][3], k2, k3);
                }
            }
        }
#pragma unroll
        for (int h = 0; h < 2; h++)
#pragma unroll
            for (int gp = 0; gp < 8; gp++) {
                asm volatile("ex2.approx.f16x2 %0, %0;\n" : "+r"(sn[h][gp][0]));
                asm volatile("ex2.approx.f16x2 %0, %0;\n" : "+r"(sn[h][gp][1]));
            }
    };

    auto l_mma = [&](uint32_t (&cur)[2][8][2]) {
#pragma unroll
        for (int h = 0; h < 2; h++)
#pragma unroll
            for (int j = 0; j < 4; j++)
                mma_h(lacc[h], cur[h][2*j][0], cur[h][2*j][1],
                      cur[h][2*j+1][0], cur[h][2*j+1][1], ONES_H2, ONES_H2);
    };

    auto pv_only = [&](uint32_t aV, uint32_t (&cur)[2][8][2]) {
#pragma unroll
        for (int j = 0; j < 4; j++) {
#pragma unroll
            for (int db = 0; db < 8; db += 2) {
                const int row = 16 * j + (lane & 15);
                const int ch  = db + (lane >> 4);
                uint32_t v0, v1, v2, v3;
                ldsm4t(aV + swz(row, ch), v0, v1, v2, v3);
#pragma unroll
                for (int h = 0; h < 2; h++) {
                    mma_h(o[h][db],     cur[h][2*j][0], cur[h][2*j][1],
                          cur[h][2*j+1][0], cur[h][2*j+1][1], v0, v1);
                    mma_h(o[h][db + 1], cur[h][2*j][0], cur[h][2*j][1],
                          cur[h][2*j+1][0], cur[h][2*j+1][1], v2, v3);
                }
            }
        }
    };

    // ping-pong body: l(cur) + PV(tt,cur) interleaved with S(tt+1)->nxt.
    auto body = [&](int tt, uint32_t (&cur)[2][8][2], uint32_t (&nxt)[2][8][2]) {
        if (tt + 2 < NT) cp_wait<1>(); else cp_wait<0>();
        __syncthreads();
        if (tt + 3 < NT) load_tile(tt + 3);

        l_mma(cur);

        const uint32_t aV = smbase + (tt & 3) * AT_STG + 8192;
        const uint32_t aK = smbase + ((tt + 1) & 3) * AT_STG;

#pragma unroll
        for (int h = 0; h < 2; h++)
#pragma unroll
            for (int gp = 0; gp < 8; gp++) { nxt[h][gp][0] = 0u; nxt[h][gp][1] = 0u; }

#pragma unroll
        for (int step = 0; step < 4; step++) {
            // PV(tt) slice j = step
#pragma unroll
            for (int db = 0; db < 8; db += 2) {
                const int row = 16 * step + (lane & 15);
                const int ch  = db + (lane >> 4);
                uint32_t v0, v1, v2, v3;
                ldsm4t(aV + swz(row, ch), v0, v1, v2, v3);
#pragma unroll
                for (int h = 0; h < 2; h++) {
                    mma_h(o[h][db],     cur[h][2*step][0], cur[h][2*step][1],
                          cur[h][2*step+1][0], cur[h][2*step+1][1], v0, v1);
                    mma_h(o[h][db + 1], cur[h][2*step][0], cur[h][2*step][1],
                          cur[h][2*step+1][0], cur[h][2*step+1][1], v2, v3);
                }
            }
            // S(tt+1) slice s = step
#pragma unroll
            for (int gp = 0; gp < 8; gp += 2) {
                const int row = 8 * (gp + (lane >> 4)) + (lane & 7);
                const int ch  = 2 * step + ((lane >> 3) & 1);
                uint32_t k0, k1, k2, k3;
                ldsm4(aK + swz(row, ch), k0, k1, k2, k3);
#pragma unroll
                for (int h = 0; h < 2; h++) {
                    mma_h16(nxt[h][gp],     qh[h][step][0], qh[h][step][1],
                            qh[h][step][2], qh[h][step][3], k0, k1);
                    mma_h16(nxt[h][gp + 1], qh[h][step][0], qh[h][step][1],
                            qh[h][step][2], qh[h][step][3], k2, k3);
                }
            }
        }

        // p = 2^s in place: nxt becomes P(tt+1)
#pragma unroll
        for (int h = 0; h < 2; h++)
#pragma unroll
            for (int gp = 0; gp < 8; gp++) {
                asm volatile("ex2.approx.f16x2 %0, %0;\n" : "+r"(nxt[h][gp][0]));
                asm volatile("ex2.approx.f16x2 %0, %0;\n" : "+r"(nxt[h][gp][1]));
            }
    };

    // ---- prologue ----
    load_tile(0);
    load_tile(1);
    cp_wait<1>();
    __syncthreads();
    s_only(smbase + 0 * AT_STG, ppA);
    load_tile(2);

    // ---- main loop: bodies tt = 0..30, then PV-only(31) ----
    int tt = 0;
#pragma unroll 1
    for (int it = 0; it < 15; it++) {
        body(tt,     ppA, ppB);
        body(tt + 1, ppB, ppA);
        tt += 2;
    }
    body(30, ppA, ppB);

    l_mma(ppB);
    pv_only(smbase + ((NT - 1) & 3) * AT_STG + 8192, ppB);

    // ---- epilogue ----
#pragma unroll
    for (int half = 0; half < 2; half++) {
        const float inv0 = 1.f / lacc[half][0], inv1 = 1.f / lacc[half][2];
#pragma unroll
        for (int g = 0; g < 8; g++) {
            const int dh = 8 * g + c2;
            const int q  = qrow + half * 16 + r4;
            size_t off = ((size_t)bb * N + q) * (H * DH) + hh * DH + dh;
            *(float2*)(out + off) = make_float2(o[half][g][0] * inv0,
                                                o[half][g][1] * inv0);
            off = ((size_t)bb * N + q + 8) * (H * DH) + hh * DH + dh;
            *(float2*)(out + off) = make_float2(o[half][g][2] * inv1,
                                                o[half][g][3] * inv1);
        }
    }
}

// ---------------------------------------------------------------------------
extern "C" void kernel_launch(void* const* d_in, const int* in_sizes, int n_in,
                              void* d_out, int out_size)
{
    const float* x = (const float*)d_in[0];   // [4, 2048, 512] fp32
    const float* wt = (const float*)d_in[1];  // [1536, 512] fp32
    float* out = (float*)d_out;               // [4, 2048, 512] fp32

    cudaFuncSetAttribute(qkv_gemm, cudaFuncAttributeMaxDynamicSharedMemorySize,
                         G_SMEM);
    cudaFuncSetAttribute(attn, cudaFuncAttributeMaxDynamicSharedMemorySize,
                         ATTN_SMEM);

    convert_all<<<CV_GRID, 256>>>(x, wt);

    dim3 g1(12, 64);                          // 1536/128, 8192/128
    qkv_gemm<<<g1, 256, G_SMEM>>>();

    dim3 g2(N / 128, H, B);                   // (16, 8, 4)
    attn<<<g2, 128, ATTN_SMEM>>>(out);
}

// round 13
// speedup vs baseline: 1.1423x; 1.1423x over previous
#include <cuda_runtime.h>
#include <cuda_fp16.h>
#include <stdint.h>

// Problem constants
constexpr int B  = 4;
constexpr int N  = 2048;
constexpr int D  = 512;
constexpr int H  = 8;
constexpr int DH = 64;
constexpr float SCALE  = 0.125f;                 // DH^-0.5
constexpr float LOG2E  = 1.4426950408889634f;
constexpr float QSCALE = SCALE * LOG2E;          // folded into Q: p = 2^s

constexpr size_t QKV_ELEMS = (size_t)B * H * N * DH;  // 4,194,304
constexpr size_t X_ELEMS   = (size_t)B * N * D;
constexpr size_t W_ELEMS   = (size_t)3 * H * DH * D;

// fp16 scratch (hi-only everywhere).
__device__ __half g_Xh[X_ELEMS];
__device__ __half g_Wh[W_ELEMS];
// Q: pre-shifted (q_cross), pre-scaled by SCALE*log2e. [bh][row][dh].
__device__ __half g_Qh[QKV_ELEMS];
__device__ __half g_K[QKV_ELEMS];
__device__ __half g_V[QKV_ELEMS];

// ---------------- helpers ----------------
__device__ __forceinline__ uint32_t smem_u32(const void* p) {
    return (uint32_t)__cvta_generic_to_shared(p);
}
__device__ __forceinline__ uint32_t swz(int row, int ch) {
    return (uint32_t)(row * 128 + ((ch ^ (row & 7)) << 4));
}
__device__ __forceinline__ void ldsm4(uint32_t a, uint32_t& r0, uint32_t& r1,
                                      uint32_t& r2, uint32_t& r3) {
    asm volatile("ldmatrix.sync.aligned.m8n8.x4.shared.b16 {%0,%1,%2,%3},[%4];\n"
                 : "=r"(r0), "=r"(r1), "=r"(r2), "=r"(r3) : "r"(a));
}
__device__ __forceinline__ void ldsm4t(uint32_t a, uint32_t& r0, uint32_t& r1,
                                       uint32_t& r2, uint32_t& r3) {
    asm volatile("ldmatrix.sync.aligned.m8n8.x4.trans.shared.b16 {%0,%1,%2,%3},[%4];\n"
                 : "=r"(r0), "=r"(r1), "=r"(r2), "=r"(r3) : "r"(a));
}
// fp32-accum fp16 MMA
__device__ __forceinline__ void mma_h(float* c, uint32_t a0, uint32_t a1,
                                      uint32_t a2, uint32_t a3,
                                      uint32_t b0, uint32_t b1) {
    asm volatile(
        "mma.sync.aligned.m16n8k16.row.col.f32.f16.f16.f32 "
        "{%0,%1,%2,%3},{%4,%5,%6,%7},{%8,%9},{%0,%1,%2,%3};\n"
        : "+f"(c[0]), "+f"(c[1]), "+f"(c[2]), "+f"(c[3])
        : "r"(a0), "r"(a1), "r"(a2), "r"(a3), "r"(b0), "r"(b1));
}
// fp16-accum fp16 MMA (C = 2 regs of packed half2)
__device__ __forceinline__ void mma_h16(uint32_t* c, uint32_t a0, uint32_t a1,
                                        uint32_t a2, uint32_t a3,
                                        uint32_t b0, uint32_t b1) {
    asm volatile(
        "mma.sync.aligned.m16n8k16.row.col.f16.f16.f16.f16 "
        "{%0,%1},{%2,%3,%4,%5},{%6,%7},{%0,%1};\n"
        : "+r"(c[0]), "+r"(c[1])
        : "r"(a0), "r"(a1), "r"(a2), "r"(a3), "r"(b0), "r"(b1));
}
__device__ __forceinline__ uint32_t packh(float x, float y) {
    __half2 v = __floats2half2_rn(x, y);
    return *reinterpret_cast<uint32_t*>(&v);
}
__device__ __forceinline__ void cp16(uint32_t s, const void* g) {
    asm volatile("cp.async.cg.shared.global [%0], [%1], 16;\n" :: "r"(s), "l"(g));
}
__device__ __forceinline__ void cp_commit() {
    asm volatile("cp.async.commit_group;\n");
}
template <int NN> __device__ __forceinline__ void cp_wait() {
    asm volatile("cp.async.wait_group %0;\n" :: "n"(NN));
}

// ---------------------------------------------------------------------------
// Kernel 0: fp32 -> fp16 (hi only). 2 independent float4 per thread (MLP=2),
// one 16B store.
// ---------------------------------------------------------------------------
constexpr int CV_XN8   = (int)(X_ELEMS / 8);           // 524,288
constexpr int CV_WN8   = (int)(W_ELEMS / 8);           // 98,304
constexpr int CV_TOTAL = CV_XN8 + CV_WN8;              // 622,592
constexpr int CV_GRID  = CV_TOTAL / 256;               // 2432 (exact)

__global__ __launch_bounds__(256) void convert_all(
    const float* __restrict__ x, const float* __restrict__ wt)
{
    const int i = blockIdx.x * 256 + threadIdx.x;
    const float4* src;
    uint4* dst;
    int j;
    if (i < CV_XN8) { src = (const float4*)x;  dst = (uint4*)g_Xh; j = i; }
    else            { src = (const float4*)wt; dst = (uint4*)g_Wh; j = i - CV_XN8; }
    const float4 a = src[2 * j];       // two independent 16B loads
    const float4 b = src[2 * j + 1];
    dst[j] = make_uint4(packh(a.x, a.y), packh(a.z, a.w),
                        packh(b.x, b.y), packh(b.z, b.w));
}

// ---------------------------------------------------------------------------
// Kernel 1: QKV projection GEMM, 1-pass fp16, cp.async 3-stage,
// one __syncthreads per k-iter (issue-at-top).
// BM=128, BN=128, BK=64; 8 warps (2m x 4n), warp tile m64 x n32.
// ---------------------------------------------------------------------------
constexpr int G_STAGE = 32768;
constexpr int G_SMEM  = 3 * G_STAGE;   // 96KB

__global__ __launch_bounds__(256, 2) void qkv_gemm()
{
    extern __shared__ __align__(1024) uint8_t sm[];

    const int t = threadIdx.x, lane = t & 31, w = t >> 5;
    const int m0 = blockIdx.y * 128, n0 = blockIdx.x * 128;
    const int wm = w >> 2, wn = w & 3;

    float acc[4][4][4];
#pragma unroll
    for (int f = 0; f < 4; f++)
#pragma unroll
        for (int g = 0; g < 4; g++)
#pragma unroll
            for (int i = 0; i < 4; i++) acc[f][g][i] = 0.f;

    auto issue = [&](int ki) {
        uint8_t* sbase = sm + (ki % 3) * G_STAGE;
        const int k0 = ki * 64;
#pragma unroll
        for (int i = 0; i < 8; i++) {
            const int lin = t + 256 * i;          // 0..2047
            const int arr = lin >> 10, idx = lin & 1023;
            const int row = idx >> 3, ch = idx & 7;
            const __half* src = (arr == 0 ? g_Xh + (size_t)(m0 + row) * D
                                          : g_Wh + (size_t)(n0 + row) * D)
                              + k0 + ch * 8;
            cp16(smem_u32(sbase + arr * 16384 + swz(row, ch)), src);
        }
        cp_commit();
    };

    constexpr int NK = D / 64;   // 8
    issue(0);
    issue(1);

    for (int ki = 0; ki < NK; ki++) {
        if (ki + 1 < NK) cp_wait<1>();
        else             cp_wait<0>();
        __syncthreads();
        if (ki + 2 < NK) issue(ki + 2);

        const uint32_t sA = smem_u32(sm) + (ki % 3) * G_STAGE;
        const uint32_t sB = sA + 16384;

#pragma unroll
        for (int s = 0; s < 4; s++) {
            uint32_t ah[4][4];
#pragma unroll
            for (int f = 0; f < 4; f++) {
                const int row = wm * 64 + f * 16 + (lane & 15);
                const int ch  = 2 * s + (lane >> 4);
                ldsm4(sA + swz(row, ch), ah[f][0], ah[f][1], ah[f][2], ah[f][3]);
            }
            uint32_t bh[4][2];
#pragma unroll
            for (int gp = 0; gp < 4; gp += 2) {
                const int row = wn * 32 + 8 * (gp + (lane >> 4)) + (lane & 7);
                const int ch  = 2 * s + ((lane >> 3) & 1);
                uint32_t r0, r1, r2, r3;
                ldsm4(sB + swz(row, ch), r0, r1, r2, r3);
                bh[gp][0] = r0; bh[gp][1] = r1; bh[gp+1][0] = r2; bh[gp+1][1] = r3;
            }
#pragma unroll
            for (int f = 0; f < 4; f++)
#pragma unroll
                for (int g = 0; g < 4; g++)
                    mma_h(acc[f][g], ah[f][0], ah[f][1], ah[f][2], ah[f][3],
                          bh[g][0], bh[g][1]);
        }
    }

    // Epilogue: fp16 scatter. Q pre-shifted + pre-scaled by SCALE*log2e.
    const int which = n0 >> 9;   // 0=Q, 1=K, 2=V
#pragma unroll
    for (int f = 0; f < 4; f++) {
#pragma unroll
        for (int g = 0; g < 4; g++) {
            const int c  = n0 + wn * 32 + 8 * g + 2 * (lane & 3);
            const int hh = (c >> 6) & 7;
            const int dh = c & 63;
#pragma unroll
            for (int half = 0; half < 2; half++) {
                const int m = m0 + wm * 64 + f * 16 + (lane >> 2) + half * 8;
                float v0 = acc[f][g][half * 2], v1 = acc[f][g][half * 2 + 1];
                const int bb = m >> 11, n = m & 2047;
                const size_t bhN = (size_t)(bb * H + hh) * N;
                if (which == 0) {
                    v0 *= QSCALE; v1 *= QSCALE;
                    const uint32_t hi = packh(v0, v1);
                    if (n < N - 1) *(uint32_t*)(g_Qh + (bhN + n + 1) * DH + dh) = hi;
                    if (n == 0)    *(uint32_t*)(g_Qh + bhN * DH + dh)           = hi;
                } else {
                    const size_t e = (bhN + n) * DH + dh;
                    const uint32_t hi = packh(v0, v1);
                    if (which == 1) *(uint32_t*)(g_K + e) = hi;
                    else            *(uint32_t*)(g_V + e) = hi;
                }
            }
        }
    }
}

// ---------------------------------------------------------------------------
// Kernel 2: flash attention, ping-pong pipeline, 4-stage cp.async ring,
// one __syncthreads per tile. 4 warps, m32 warp tiles, fp16 S-accum,
// ex2 in place, fp32 ones-MMA l. 2 CTAs/SM (R11 config -- 3 regressed).
// ---------------------------------------------------------------------------
constexpr int AT_STG    = 16384;
constexpr int ATTN_SMEM = 4 * AT_STG;   // 64KB
constexpr int NT = N / 64;   // 32 tiles
constexpr uint32_t ONES_H2 = 0x3C003C00u;   // packed half2 (1.0, 1.0)

__global__ __launch_bounds__(128, 2) void attn(float* __restrict__ out)
{
    extern __shared__ __align__(1024) uint8_t sm[];

    const int t = threadIdx.x, lane = t & 31, w = t >> 5;   // w: 0..3
    const int q0 = blockIdx.x * 128, hh = blockIdx.y, bb = blockIdx.z;
    const size_t base = (size_t)(bb * H + hh) * N * DH;
    const int qrow = q0 + w * 32;                // 32 queries per warp
    const int r4 = lane >> 2, c2 = 2 * (lane & 3);
    const uint32_t smbase = smem_u32(sm);

    auto load_tile = [&](int tt) {
        uint8_t* stg = sm + (tt & 3) * AT_STG;
        const int kt = tt * 64;
#pragma unroll
        for (int i = 0; i < 8; i++) {
            const int g = t + 128 * i;            // 0..1023
            const int arr = g >> 9, idx = g & 511;
            const int row = idx >> 3, ch = idx & 7;
            const __half* src = (arr == 0 ? g_K : g_V)
                              + base + (size_t)(kt + row) * DH + ch * 8;
            cp16(smem_u32(stg + arr * 8192 + swz(row, ch)), src);
        }
        cp_commit();
    };

    // Q A-fragments straight from gmem: two m16 halves
    uint32_t qh[2][4][4];
    {
        const uint32_t* ph = reinterpret_cast<const uint32_t*>(g_Qh + base);
#pragma unroll
        for (int half = 0; half < 2; half++) {
#pragma unroll
            for (int s = 0; s < 4; s++) {
                const int k = s * 16 + c2;
                const int i0 = ((qrow + half * 16 + r4) * DH + k) >> 1;
                const int i1 = ((qrow + half * 16 + r4 + 8) * DH + k) >> 1;
                qh[half][s][0] = ph[i0];     qh[half][s][1] = ph[i1];
                qh[half][s][2] = ph[i0 + 4]; qh[half][s][3] = ph[i1 + 4];
            }
        }
    }

    float o[2][8][4];
#pragma unroll
    for (int half = 0; half < 2; half++)
#pragma unroll
        for (int g = 0; g < 8; g++)
#pragma unroll
            for (int i = 0; i < 4; i++) o[half][g][i] = 0.f;
    float lacc[2][4] = {{0.f, 0.f, 0.f, 0.f}, {0.f, 0.f, 0.f, 0.f}};

    uint32_t ppA[2][8][2], ppB[2][8][2];

    // S phase only (prologue): S(tile) from stage aK into sn, then ex2
    auto s_only = [&](uint32_t aK, uint32_t (&sn)[2][8][2]) {
#pragma unroll
        for (int h = 0; h < 2; h++)
#pragma unroll
            for (int gp = 0; gp < 8; gp++) { sn[h][gp][0] = 0u; sn[h][gp][1] = 0u; }
#pragma unroll
        for (int s = 0; s < 4; s++) {
#pragma unroll
            for (int gp = 0; gp < 8; gp += 2) {
                const int row = 8 * (gp + (lane >> 4)) + (lane & 7);
                const int ch  = 2 * s + ((lane >> 3) & 1);
                uint32_t k0, k1, k2, k3;
                ldsm4(aK + swz(row, ch), k0, k1, k2, k3);
#pragma unroll
                for (int h = 0; h < 2; h++) {
                    mma_h16(sn[h][gp],     qh[h][s][0], qh[h][s][1],
                            qh[h][s][2], qh[h][s][3], k0, k1);
                    mma_h16(sn[h][gp + 1], qh[h][s][0], qh[h][s][1],
                            qh[h][s][2], qh[h][s][3], k2, k3);
                }
            }
        }
#pragma unroll
        for (int h = 0; h < 2; h++)
#pragma unroll
            for (int gp = 0; gp < 8; gp++) {
                asm volatile("ex2.approx.f16x2 %0, %0;\n" : "+r"(sn[h][gp][0]));
                asm volatile("ex2.approx.f16x2 %0, %0;\n" : "+r"(sn[h][gp][1]));
            }
    };

    auto l_mma = [&](uint32_t (&cur)[2][8][2]) {
#pragma unroll
        for (int h = 0; h < 2; h++)
#pragma unroll
            for (int j = 0; j < 4; j++)
                mma_h(lacc[h], cur[h][2*j][0], cur[h][2*j][1],
                      cur[h][2*j+1][0], cur[h][2*j+1][1], ONES_H2, ONES_H2);
    };

    auto pv_only = [&](uint32_t aV, uint32_t (&cur)[2][8][2]) {
#pragma unroll
        for (int j = 0; j < 4; j++) {
#pragma unroll
            for (int db = 0; db < 8; db += 2) {
                const int row = 16 * j + (lane & 15);
                const int ch  = db + (lane >> 4);
                uint32_t v0, v1, v2, v3;
                ldsm4t(aV + swz(row, ch), v0, v1, v2, v3);
#pragma unroll
                for (int h = 0; h < 2; h++) {
                    mma_h(o[h][db],     cur[h][2*j][0], cur[h][2*j][1],
                          cur[h][2*j+1][0], cur[h][2*j+1][1], v0, v1);
                    mma_h(o[h][db + 1], cur[h][2*j][0], cur[h][2*j][1],
                          cur[h][2*j+1][0], cur[h][2*j+1][1], v2, v3);
                }
            }
        }
    };

    // ping-pong body: l(cur) + PV(tt,cur) interleaved with S(tt+1)->nxt.
    auto body = [&](int tt, uint32_t (&cur)[2][8][2], uint32_t (&nxt)[2][8][2]) {
        if (tt + 2 < NT) cp_wait<1>(); else cp_wait<0>();
        __syncthreads();
        if (tt + 3 < NT) load_tile(tt + 3);

        l_mma(cur);

        const uint32_t aV = smbase + (tt & 3) * AT_STG + 8192;
        const uint32_t aK = smbase + ((tt + 1) & 3) * AT_STG;

#pragma unroll
        for (int h = 0; h < 2; h++)
#pragma unroll
            for (int gp = 0; gp < 8; gp++) { nxt[h][gp][0] = 0u; nxt[h][gp][1] = 0u; }

#pragma unroll
        for (int step = 0; step < 4; step++) {
            // PV(tt) slice j = step
#pragma unroll
            for (int db = 0; db < 8; db += 2) {
                const int row = 16 * step + (lane & 15);
                const int ch  = db + (lane >> 4);
                uint32_t v0, v1, v2, v3;
                ldsm4t(aV + swz(row, ch), v0, v1, v2, v3);
#pragma unroll
                for (int h = 0; h < 2; h++) {
                    mma_h(o[h][db],     cur[h][2*step][0], cur[h][2*step][1],
                          cur[h][2*step+1][0], cur[h][2*step+1][1], v0, v1);
                    mma_h(o[h][db + 1], cur[h][2*step][0], cur[h][2*step][1],
                          cur[h][2*step+1][0], cur[h][2*step+1][1], v2, v3);
                }
            }
            // S(tt+1) slice s = step
#pragma unroll
            for (int gp = 0; gp < 8; gp += 2) {
                const int row = 8 * (gp + (lane >> 4)) + (lane & 7);
                const int ch  = 2 * step + ((lane >> 3) & 1);
                uint32_t k0, k1, k2, k3;
                ldsm4(aK + swz(row, ch), k0, k1, k2, k3);
#pragma unroll
                for (int h = 0; h < 2; h++) {
                    mma_h16(nxt[h][gp],     qh[h][step][0], qh[h][step][1],
                            qh[h][step][2], qh[h][step][3], k0, k1);
                    mma_h16(nxt[h][gp + 1], qh[h][step][0], qh[h][step][1],
                            qh[h][step][2], qh[h][step][3], k2, k3);
                }
            }
        }

        // p = 2^s in place: nxt becomes P(tt+1)
#pragma unroll
        for (int h = 0; h < 2; h++)
#pragma unroll
            for (int gp = 0; gp < 8; gp++) {
                asm volatile("ex2.approx.f16x2 %0, %0;\n" : "+r"(nxt[h][gp][0]));
                asm volatile("ex2.approx.f16x2 %0, %0;\n" : "+r"(nxt[h][gp][1]));
            }
    };

    // ---- prologue ----
    load_tile(0);
    load_tile(1);
    cp_wait<1>();
    __syncthreads();
    s_only(smbase + 0 * AT_STG, ppA);
    load_tile(2);

    // ---- main loop: bodies tt = 0..30, then PV-only(31) ----
    int tt = 0;
#pragma unroll 1
    for (int it = 0; it < 15; it++) {
        body(tt,     ppA, ppB);
        body(tt + 1, ppB, ppA);
        tt += 2;
    }
    body(30, ppA, ppB);

    l_mma(ppB);
    pv_only(smbase + ((NT - 1) & 3) * AT_STG + 8192, ppB);

    // ---- epilogue ----
#pragma unroll
    for (int half = 0; half < 2; half++) {
        const float inv0 = 1.f / lacc[half][0], inv1 = 1.f / lacc[half][2];
#pragma unroll
        for (int g = 0; g < 8; g++) {
            const int dh = 8 * g + c2;
            const int q  = qrow + half * 16 + r4;
            size_t off = ((size_t)bb * N + q) * (H * DH) + hh * DH + dh;
            *(float2*)(out + off) = make_float2(o[half][g][0] * inv0,
                                                o[half][g][1] * inv0);
            off = ((size_t)bb * N + q + 8) * (H * DH) + hh * DH + dh;
            *(float2*)(out + off) = make_float2(o[half][g][2] * inv1,
                                                o[half][g][3] * inv1);
        }
    }
}

// ---------------------------------------------------------------------------
extern "C" void kernel_launch(void* const* d_in, const int* in_sizes, int n_in,
                              void* d_out, int out_size)
{
    const float* x = (const float*)d_in[0];   // [4, 2048, 512] fp32
    const float* wt = (const float*)d_in[1];  // [1536, 512] fp32
    float* out = (float*)d_out;               // [4, 2048, 512] fp32

    cudaFuncSetAttribute(qkv_gemm, cudaFuncAttributeMaxDynamicSharedMemorySize,
                         G_SMEM);
    cudaFuncSetAttribute(attn, cudaFuncAttributeMaxDynamicSharedMemorySize,
                         ATTN_SMEM);

    convert_all<<<CV_GRID, 256>>>(x, wt);

    dim3 g1(12, 64);                          // 1536/128, 8192/128
    qkv_gemm<<<g1, 256, G_SMEM>>>();

    dim3 g2(N / 128, H, B);                   // (16, 8, 4)
    attn<<<g2, 128, ATTN_SMEM>>>(out);
}